// round 12
// baseline (speedup 1.0000x reference)
#include <cuda_runtime.h>
#include <cstdint>

// Shapes: x[8,64,512,512] f32, W[64,64], b[64], seg_w[4,4] -> out[8,64,512,512]
// SEG=4 -> 128x128 blocks. A "band" = one (b,c,i) slab of 128 rows = 16384 float4.
// 2048 bands. Measured ceilings: read 6.94 TB/s, write ~6.9 TB/s (LTS cap);
// fixed harness overhead ~16us. Structure: pool(+fused linear) -> bcast.
#define Bb 8
#define Cc 64
#define Oo 64
#define BAND_F4 16384
#define NBAND   2048

// scratch (__device__ globals: allocation-free rule)
__device__ float g_pooled[Bb*Cc*16];     // [b][c][i*4+j], mean-scaled
__device__ float g_weighted[Bb*Oo*16];   // [b][o][i*4+j]
__device__ int   g_cnt[Bb];              // per-batch pool arrival counters

// ---------------------------------------------------------------------------
// Kernel 1: segment mean pool + fused per-batch linear.
// One CTA per band (b,c,i) -- R1's exact streaming body. The last CTA to
// finish a batch (counter hits 256) computes that batch's 64x16 linear
// outputs, overlapped with other batches' pool CTAs.
// ---------------------------------------------------------------------------
__global__ void __launch_bounds__(256, 8) pool_kernel(
    const float4* __restrict__ x,
    const float*  __restrict__ Wm,
    const float*  __restrict__ bias,
    const float*  __restrict__ segw)
{
    const int tid = threadIdx.x;
    const int g   = blockIdx.x;                 // band index 0..2047
    const float4* base = x + (size_t)g * BAND_F4;

    float acc = 0.0f;
    #pragma unroll 8
    for (int idx = tid; idx < BAND_F4; idx += 256) {
        float4 v = base[idx];
        acc += (v.x + v.y) + (v.z + v.w);
    }

    #pragma unroll
    for (int off = 16; off; off >>= 1)
        acc += __shfl_xor_sync(0xffffffffu, acc, off);

    __shared__ float ws[8];
    __shared__ int   s_last;
    const int warp = tid >> 5;
    if ((tid & 31) == 0) ws[warp] = acc;        // warp w covers j = w&3
    __syncthreads();

    const int b = g >> 8;                       // batch = band/256
    if (tid == 0) {
        const float inv = 1.0f / 16384.0f;
        float* dst = g_pooled + (g >> 2) * 16 + (g & 3) * 4;
        dst[0] = (ws[0] + ws[4]) * inv;
        dst[1] = (ws[1] + ws[5]) * inv;
        dst[2] = (ws[2] + ws[6]) * inv;
        dst[3] = (ws[3] + ws[7]) * inv;
        __threadfence();                        // release pooled values
        s_last = (atomicAdd(&g_cnt[b], 1) == 255);
    } else if (tid < 4) {
        // redundant writes avoided: tid 0 writes all 4 cells above
    }
    __syncthreads();

    if (s_last) {
        __threadfence();                        // acquire all batch-b pools
        // linear for batch b: 1024 outputs, 4 per thread
        #pragma unroll
        for (int k = 0; k < 4; k++) {
            const int idx2 = tid + k * 256;
            const int o = idx2 >> 4, ij = idx2 & 15;
            const float* p  = g_pooled + (b * Cc) * 16 + ij;
            const float* wr = Wm + o * Cc;
            float a = bias[o];
            #pragma unroll 8
            for (int c = 0; c < Cc; c++)
                a = fmaf(__ldcg(&p[c * 16]), wr[c], a);
            g_weighted[(b * Oo + o) * 16 + ij] = a * segw[ij];
        }
    }
}

// ---------------------------------------------------------------------------
// Kernel 2: broadcast (R1's exact body). One CTA per band (b,o,i); each
// thread's column segment j is loop-invariant; pure float4 streaming stores.
// Also resets g_cnt for the next graph replay (pool is quiescent now).
// ---------------------------------------------------------------------------
__global__ __launch_bounds__(256) void bcast_kernel(float4* __restrict__ out)
{
    if (blockIdx.x == 0 && threadIdx.x < Bb) g_cnt[threadIdx.x] = 0;

    const int g  = blockIdx.x;                  // band index 0..2047
    const int bo = g >> 2;                      // b*O + o
    const int i  = g & 3;

    const float* wv = g_weighted + bo * 16 + i * 4;
    const int j = (threadIdx.x & 127) >> 5;     // fixed per thread
    const float v = wv[j];
    const float4 f = make_float4(v, v, v, v);

    float4* base = out + (size_t)bo * (4 * BAND_F4) + (size_t)i * BAND_F4;

    #pragma unroll 8
    for (int idx = threadIdx.x; idx < BAND_F4; idx += 256)
        base[idx] = f;
}

// ---------------------------------------------------------------------------
extern "C" void kernel_launch(void* const* d_in, const int* in_sizes, int n_in,
                              void* d_out, int out_size)
{
    const float4* x    = (const float4*)d_in[0];
    const float*  Wm   = (const float*)d_in[1];
    const float*  bias = (const float*)d_in[2];
    const float*  segw = (const float*)d_in[3];
    float4* out = (float4*)d_out;

    pool_kernel<<<NBAND, 256>>>(x, Wm, bias, segw);
    bcast_kernel<<<NBAND, 256>>>(out);
}